// round 16
// baseline (speedup 1.0000x reference)
#include <cuda_runtime.h>
#include <cuda_fp16.h>
#include <cstdint>
#include <stdint.h>
#include <math.h>

namespace {

typedef unsigned int u32;
typedef unsigned long long u64;

constexpr int B_  = 16;
constexpr int N_  = 512;
constexpr int K_  = 48;
constexpr int D_  = 128;
constexpr int KP1 = 49;
constexpr int ATOMS = 4;
constexpr int THREADS = 512;
constexpr int NATOM = B_ * N_;        // 8192

constexpr int KVH  = 136;             // half stride per kv row
constexpr int KVAH = KP1 * KVH;       // 6664 halfs per atom kv tile

// main-kernel smem word offsets (liveness audited)
constexpr int SKV   = 0;       // kv half 4*6664 = 13328 w [E..G]
constexpr int SA    = 13328;   // gaussian f half tile 256 x 40 halfs = 5120 w [B..E]
constexpr int SSC   = 13328;   // score partials 4096 w (alias, SA dead)      [F..softmax]
constexpr int SATT  = 18448;   // attn half [a][64][8] = 1024 w               [softmax..G]
constexpr int SB    = 19472;   // filtW half 32*136 = 2176 w                  [start..E]
constexpr int SPH   = 21648;   // p half [a][8][136] = 2176 w — own region    [prologue..F]
constexpr int SC_   = 23824;   // 256
constexpr int SLR   = 24080;   // 256
constexpr int SMK   = 24336;   // 256
constexpr int SZJ   = 24592;   // 256 ints
constexpr int SMEM_FLOATS = 24848;
constexpr int SMEM_BYTES  = SMEM_FLOATS * 4;   // 99392 -> 2 CTAs/SM

// intermediate device buffers (static scratch — allowed)
__device__ __half g_M [128 * 1024];     // M[e][h*128+d]
__device__ __half g_V3[1024 * 128];     // V3[(d*8+h)][co]
__device__ __half g_P [NATOM * 1024];   // p[atom][h*128+d]
__device__ __half g_U [NATOM * 1024];   // u[atom][d*8+h]

__device__ __forceinline__ void ldsm4(u32* r, u32 a) {
    asm volatile("ldmatrix.sync.aligned.m8n8.x4.shared.b16 {%0,%1,%2,%3}, [%4];"
        : "=r"(r[0]), "=r"(r[1]), "=r"(r[2]), "=r"(r[3]) : "r"(a));
}
__device__ __forceinline__ void ldsm4t(u32* r, u32 a) {
    asm volatile("ldmatrix.sync.aligned.m8n8.x4.trans.shared.b16 {%0,%1,%2,%3}, [%4];"
        : "=r"(r[0]), "=r"(r[1]), "=r"(r[2]), "=r"(r[3]) : "r"(a));
}
__device__ __forceinline__ void mma16816(float* acc, const u32* a,
                                         u32 b0, u32 b1) {
    asm volatile(
        "mma.sync.aligned.m16n8k16.row.col.f32.f16.f16.f32 "
        "{%0,%1,%2,%3}, {%4,%5,%6,%7}, {%8,%9}, {%0,%1,%2,%3};"
        : "+f"(acc[0]), "+f"(acc[1]), "+f"(acc[2]), "+f"(acc[3])
        : "r"(a[0]), "r"(a[1]), "r"(a[2]), "r"(a[3]), "r"(b0), "r"(b1));
}
__device__ __forceinline__ u32 smem_u32(const void* p) {
    return (u32)__cvta_generic_to_shared(const_cast<void*>(p));
}
// fast 2^t for t <= 0: floor/frac + deg-3 poly, no MUFU
__device__ __forceinline__ float exp2_fast(float t) {
    t = fmaxf(t, -126.0f);
    const float fl = floorf(t);
    const float fr = t - fl;
    float p = __fmaf_rn(fr, 0.0781455737f, 0.226173243f);
    p = __fmaf_rn(fr, p, 0.695556856f);
    p = __fmaf_rn(fr, p, 1.0f);
    const int ei = ((int)fl + 127) << 23;
    return __int_as_float(ei) * p;
}

// ============ Kernel W: precompute M and V3 ============
__global__ void __launch_bounds__(256)
prep_kernel(const float* __restrict__ Wq, const float* __restrict__ Wk,
            const float* __restrict__ Wv, const float* __restrict__ Wo)
{
    const int idx = blockIdx.x * 256 + threadIdx.x;
    if (idx < 131072) {
        const int e = idx >> 10, k = idx & 1023, h = k >> 7, d = k & 127;
        const float* qa = Wq + e * 128 + h * 16;
        const float* ka = Wk + d * 128 + h * 16;
        float s = 0.f;
        #pragma unroll
        for (int c = 0; c < 16; c++) s += qa[c] * ka[c];
        g_M[e * 1024 + k] = __float2half(s);
    } else {
        const int i2 = idx - 131072;
        const int row = i2 >> 7, co = i2 & 127, d = row >> 3, h = row & 7;
        float s = 0.f;
        #pragma unroll
        for (int c = 0; c < 16; c++)
            s += Wv[d * 128 + h * 16 + c] * Wo[(h * 16 + c) * 128 + co];
        g_V3[row * 128 + co] = __float2half(s);
    }
}

// ============ Kernel P: P = X @ M  (64 atoms/CTA, mma) ============
constexpr int P_SMEM = (64 * 136 + 128 * 136) * 2;   // 52224 B
__global__ void __launch_bounds__(512, 2)
proj_kernel(const int* __restrict__ z, const float* __restrict__ embedding)
{
    extern __shared__ __half psm[];
    __half* ax = psm;                 // X tile 64 x 136
    __half* bm = psm + 64 * 136;      // M chunk 128 x 136
    const int tid  = threadIdx.x;
    const int lane = tid & 31;
    const int warp = tid >> 5;
    const int atomBase = blockIdx.x * 64;

    for (int idx = tid; idx < 64 * 128; idx += 512) {
        const int a = idx >> 7, e = idx & 127;
        ax[a * 136 + e] = __float2half(embedding[(u64)z[atomBase + a] * 128 + e]);
    }
    __syncthreads();

    const int mt = warp >> 2, nt = warp & 3;
    const int grp = lane >> 2, tg = lane & 3;
    const int lrow = mt * 16 + ((lane & 8) ? 8 : 0) + (lane & 7);
    const int lcol = (lane & 16) ? 8 : 0;
    const int brow = ((lane & 8) ? 8 : 0) + (lane & 7);
    const int bcol = (lane & 16) ? 8 : 0;
    u32 afr[8][4];
    #pragma unroll
    for (int kk = 0; kk < 8; kk++)
        ldsm4(afr[kk], smem_u32(ax + lrow * 136 + kk * 16 + lcol));

    for (int kc = 0; kc < 8; kc++) {
        for (int u = tid; u < 2048; u += 512) {
            const int er = u >> 4, seg = u & 15;
            *(uint4*)&bm[er * 136 + seg * 8] =
                *(const uint4*)&g_M[er * 1024 + kc * 128 + seg * 8];
        }
        __syncthreads();
        float acc[4][4];
        #pragma unroll
        for (int i = 0; i < 4; i++)
            #pragma unroll
            for (int j2 = 0; j2 < 4; j2++) acc[i][j2] = 0.f;
        #pragma unroll
        for (int kk = 0; kk < 8; kk++) {
            #pragma unroll
            for (int np = 0; np < 2; np++) {
                u32 bfr[4];
                ldsm4t(bfr, smem_u32(bm + (kk * 16 + brow) * 136 + nt * 32 + np * 16 + bcol));
                mma16816(acc[np * 2 + 0], afr[kk], bfr[0], bfr[1]);
                mma16816(acc[np * 2 + 1], afr[kk], bfr[2], bfr[3]);
            }
        }
        #pragma unroll
        for (int t8 = 0; t8 < 4; t8++) {
            const int col = kc * 128 + nt * 32 + (t8 >> 1) * 16 + (t8 & 1) * 8 + tg * 2;
            const int r0 = atomBase + mt * 16 + grp;
            *(__half2*)&g_P[(u32)r0 * 1024 + col] =
                __floats2half2_rn(acc[t8][0], acc[t8][1]);
            *(__half2*)&g_P[(u32)(r0 + 8) * 1024 + col] =
                __floats2half2_rn(acc[t8][2], acc[t8][3]);
        }
        __syncthreads();
    }
}

// ============ Kernel O: out = X + U @ V3  (64 atoms/CTA, mma) ============
constexpr int O_SMEM = (64 * 136 + 128 * 136) * 2;   // 52224 B
__global__ void __launch_bounds__(512, 2)
outp_kernel(const int* __restrict__ z, const float* __restrict__ embedding,
            float* __restrict__ out)
{
    extern __shared__ __half osm[];
    __half* ua = osm;                 // U chunk 64 x 136
    __half* bv = osm + 64 * 136;      // V3 chunk 128 x 136
    const int tid  = threadIdx.x;
    const int lane = tid & 31;
    const int warp = tid >> 5;
    const int atomBase = blockIdx.x * 64;

    const int mt = warp >> 2, nq = warp & 3;
    const int grp = lane >> 2, tg = lane & 3;
    const int lrow = mt * 16 + ((lane & 8) ? 8 : 0) + (lane & 7);
    const int lcol = (lane & 16) ? 8 : 0;
    const int brow = ((lane & 8) ? 8 : 0) + (lane & 7);
    const int bcol = (lane & 16) ? 8 : 0;

    float acc[4][4];
    #pragma unroll
    for (int i = 0; i < 4; i++)
        #pragma unroll
        for (int j2 = 0; j2 < 4; j2++) acc[i][j2] = 0.f;

    for (int kc = 0; kc < 8; kc++) {
        for (int u = tid; u < 1024; u += 512) {
            const int a = u >> 4, seg = u & 15;
            *(uint4*)&ua[a * 136 + seg * 8] =
                *(const uint4*)&g_U[(u32)(atomBase + a) * 1024 + kc * 128 + seg * 8];
        }
        for (int u = tid; u < 2048; u += 512) {
            const int r = u >> 4, seg = u & 15;
            *(uint4*)&bv[r * 136 + seg * 8] =
                *(const uint4*)&g_V3[(kc * 128 + r) * 128 + seg * 8];
        }
        __syncthreads();
        u32 afr[8][4];
        #pragma unroll
        for (int kk = 0; kk < 8; kk++)
            ldsm4(afr[kk], smem_u32(ua + lrow * 136 + kk * 16 + lcol));
        #pragma unroll
        for (int kk = 0; kk < 8; kk++) {
            #pragma unroll
            for (int np = 0; np < 2; np++) {
                u32 bfr[4];
                ldsm4t(bfr, smem_u32(bv + (kk * 16 + brow) * 136 + nq * 32 + np * 16 + bcol));
                mma16816(acc[np * 2 + 0], afr[kk], bfr[0], bfr[1]);
                mma16816(acc[np * 2 + 1], afr[kk], bfr[2], bfr[3]);
            }
        }
        __syncthreads();
    }
    const int r0 = atomBase + mt * 16 + grp;
    const int r1 = r0 + 8;
    const int z0 = z[r0], z1 = z[r1];
    #pragma unroll
    for (int t8 = 0; t8 < 4; t8++) {
        const int co = nq * 32 + (t8 >> 1) * 16 + (t8 & 1) * 8 + tg * 2;
        const float2 x0 = *(const float2*)&embedding[(u64)z0 * 128 + co];
        const float2 x1 = *(const float2*)&embedding[(u64)z1 * 128 + co];
        float2 o0, o1;
        o0.x = x0.x + acc[t8][0]; o0.y = x0.y + acc[t8][1];
        o1.x = x1.x + acc[t8][2]; o1.y = x1.y + acc[t8][3];
        *(float2*)&out[r0 * 128 + co] = o0;
        *(float2*)&out[r1 * 128 + co] = o1;
    }
}

// ============ Main kernel: A/B/E/F/softmax/G ============
__global__ void __launch_bounds__(THREADS, 2)
tdt_kernel(const float* __restrict__ positions,
           const int*   __restrict__ z,
           const int*   __restrict__ neighbors,
           const float* __restrict__ nmask,
           const float* __restrict__ embedding,
           const float* __restrict__ filtW,
           const float* __restrict__ filtb)
{
    extern __shared__ __align__(16) float sm[];
    int*    smi = (int*)sm;
    __half* kvh = (__half*)sm;            // kv tile at word 0

    const int tid  = threadIdx.x;
    const int lane = tid & 31;
    const int warp = tid >> 5;            // 0..15
    const int a4   = tid >> 7;            // 0..3

    const int atomBase = blockIdx.x * ATOMS;

    // filtW -> half B tile (stride 136)
    {
        __half* bb = (__half*)sm + SB * 2;
        for (int idx = tid; idx < 32 * 128; idx += THREADS) {
            bb[(idx >> 7) * 136 + (idx & 127)] = __float2half(filtW[idx]);
        }
    }
    // P -> SPH copy (own region; sealed by syncs before F)
    {
        __half* ph = (__half*)sm + SPH * 2;
        const int u = tid;                // 512 units x 8 halfs = 4096
        const int a = u >> 7;
        const int rem = u & 127;
        const int h = rem >> 4;
        const int seg = rem & 15;
        *(uint4*)&ph[a * 1088 + h * 136 + seg * 8] =
            *(const uint4*)&g_P[(u32)(atomBase + a) * 1024 + h * 128 + seg * 8];
    }

    // ---- Phase A: per-neighbor scalars (4 atoms x 49 j) ----
    if (tid < 256) {
        const int a = tid >> 6;
        const int j = tid & 63;
        if (j < KP1) {
            const int atom = atomBase + a;
            const int b    = atom >> 9;
            float r, mk; int zjv;
            if (j == 0) { r = 0.01f; mk = 1.0f; zjv = z[atom]; }
            else {
                const int nb = neighbors[atom * K_ + j - 1];
                const float dx = positions[(b * N_ + nb) * 3 + 0] - positions[atom * 3 + 0];
                const float dy = positions[(b * N_ + nb) * 3 + 1] - positions[atom * 3 + 1];
                const float dz = positions[(b * N_ + nb) * 3 + 2] - positions[atom * 3 + 2];
                r   = sqrtf(dx * dx + dy * dy + dz * dz + 1e-12f);
                mk  = nmask[atom * K_ + j - 1];
                zjv = z[b * N_ + nb];
            }
            sm[SLR + a * 64 + j] = __logf(r);
            sm[SC_ + a * 64 + j] = (r < 5.0f) ? (0.5f * (__cosf(r * 0.6283185307f) + 1.0f)) : 0.0f;
            sm[SMK + a * 64 + j] = mk;
            smi[SZJ + a * 64 + j] = zjv;
        }
    }
    __syncthreads();

    // ---- Phase B: gaussians via exp2_fast -> fp16 A tile (stride 40 halfs) ----
    {
        const float OFF0  = -2.3025850930f;
        const float STEP  =  0.1261942905f;
        const float COEFF2 = (-0.5f / (STEP * STEP)) * 1.4426950409f;
        __half2* ah = (__half2*)sm;       // half2 index == word index
        for (int idx = tid; idx < ATOMS * KP1 * 16; idx += THREADS) {
            const int a   = idx / 784;
            const int rem = idx - a * 784;
            const int j   = rem >> 4;
            const int gp  = rem & 15;
            const float lr = sm[SLR + a * 64 + j];
            const float o0 = OFF0 + STEP * (float)(2 * gp);
            const float d0 = lr - o0;
            const float d1 = lr - (o0 + STEP);
            const float e0 = exp2_fast(COEFF2 * d0 * d0);
            const float e1 = exp2_fast(COEFF2 * d1 * d1);
            ah[SA + (a * 64 + j) * 20 + gp] = __floats2half2_rn(e0, e1);
        }
        for (int idx = tid; idx < ATOMS * 15 * 16; idx += THREADS) {
            const int a   = idx / 240;
            const int rem = idx - a * 240;
            const int j   = 49 + (rem >> 4);
            const int gp  = rem & 15;
            ah[SA + (a * 64 + j) * 20 + gp] = __floats2half2_rn(0.f, 0.f);
        }
    }
    __syncthreads();

    // ---- Phase E: tensor-core filter GEMM + epilogue -> kv (half) ----
    {
        const int wA   = warp >> 2;
        const int grp  = lane >> 2;
        const int tg   = lane & 3;
        const int jj0  = (warp & 3) * 16 + grp;
        const int jj1  = jj0 + 8;
        const bool ok0 = jj0 < KP1, ok1 = jj1 < KP1;
        const int   zj0 = ok0 ? smi[SZJ + wA * 64 + jj0] : 0;
        const int   zj1 = ok1 ? smi[SZJ + wA * 64 + jj1] : 0;
        const float Cc0 = ok0 ? sm[SC_ + wA * 64 + jj0] : 0.f;
        const float Cc1 = ok1 ? sm[SC_ + wA * 64 + jj1] : 0.f;
        const float* em0 = embedding + (u64)zj0 * D_;
        const float* em1 = embedding + (u64)zj1 * D_;
        __half* kvb = kvh + wA * KVAH;

        u32 afr[2][4];
        {
            const __half* ab = (const __half*)sm + SA * 2;
            const int lrow = warp * 16 + ((lane & 8) ? 8 : 0) + (lane & 7);
            const int lcol = (lane & 16) ? 8 : 0;
            ldsm4(afr[0], smem_u32(ab + lrow * 40 + lcol));
            ldsm4(afr[1], smem_u32(ab + lrow * 40 + 16 + lcol));
        }
        const __half* bb = (const __half*)sm + SB * 2;
        const int brow = ((lane & 8) ? 8 : 0) + (lane & 7);
        const int bcol = (lane & 16) ? 8 : 0;

        #pragma unroll
        for (int np = 0; np < 8; np++) {
            float acc[8] = {0.f,0.f,0.f,0.f,0.f,0.f,0.f,0.f};
            #pragma unroll
            for (int kk = 0; kk < 2; kk++) {
                u32 bfr[4];
                ldsm4t(bfr, smem_u32(bb + (kk * 16 + brow) * 136 + np * 16 + bcol));
                mma16816(acc + 0, afr[kk], bfr[0], bfr[1]);
                mma16816(acc + 4, afr[kk], bfr[2], bfr[3]);
            }
            #pragma unroll
            for (int t = 0; t < 2; t++) {
                const int c0 = np * 16 + t * 8 + tg * 2;
                const float2 fb2 = *(const float2*)&filtb[c0];
                if (ok0) {
                    const float2 e2 = *(const float2*)&em0[c0];
                    const float v0 = (acc[t*4+0] + fb2.x) * Cc0 * e2.x;
                    const float v1 = (acc[t*4+1] + fb2.y) * Cc0 * e2.y;
                    *(__half2*)&kvb[jj0 * KVH + c0] = __floats2half2_rn(v0, v1);
                }
                if (ok1) {
                    const float2 e2 = *(const float2*)&em1[c0];
                    const float v0 = (acc[t*4+2] + fb2.x) * Cc1 * e2.x;
                    const float v1 = (acc[t*4+3] + fb2.y) * Cc1 * e2.y;
                    *(__half2*)&kvb[jj1 * KVH + c0] = __floats2half2_rn(v0, v1);
                }
            }
        }
    }
    __syncthreads();

    // ---- Phase F: partial scores in HALF2; warp = (a, rep, dhalf) ----
    {
        const int a     = warp >> 2;
        const int rep   = (warp >> 1) & 1;
        const int dhalf = warp & 1;
        const int j     = rep * 32 + lane;
        __half2 acc2[8];
        #pragma unroll
        for (int h = 0; h < 8; h++) acc2[h] = __floats2half2_rn(0.f, 0.f);
        if (j < KP1) {
            const uint4* kvr = (const uint4*)&kvh[a * KVAH + j * KVH + dhalf * 64];
            const __half* pb = (const __half*)sm + SPH * 2 + a * 1088 + dhalf * 64;
            #pragma unroll
            for (int c8 = 0; c8 < 8; c8++) {
                const uint4 kraw = kvr[c8];
                const __half2 k01 = *(const __half2*)&kraw.x;
                const __half2 k23 = *(const __half2*)&kraw.y;
                const __half2 k45 = *(const __half2*)&kraw.z;
                const __half2 k67 = *(const __half2*)&kraw.w;
                #pragma unroll
                for (int h = 0; h < 8; h++) {
                    const uint4 praw = *(const uint4*)&pb[h * 136 + c8 * 8];
                    __half2 t = __hmul2(k01, *(const __half2*)&praw.x);
                    t = __hfma2(k23, *(const __half2*)&praw.y, t);
                    t = __hfma2(k45, *(const __half2*)&praw.z, t);
                    t = __hfma2(k67, *(const __half2*)&praw.w, t);
                    acc2[h] = __hadd2(acc2[h], t);
                }
            }
        }
        #pragma unroll
        for (int h = 0; h < 8; h++)
            sm[SSC + (warp * 8 + h) * 32 + lane] =
                __low2float(acc2[h]) + __high2float(acc2[h]);
    }
    __syncthreads();

    // ---- softmax: warp = (apair, head); writes fp16 attn [a][j][8] ----
    {
        const int h  = warp & 7;
        const int ap = warp >> 3;
        __half* atth = (__half*)sm + SATT * 2;
        #pragma unroll
        for (int aa = 0; aa < 2; aa++) {
            const int a = ap * 2 + aa;
            float v0 = sm[SSC + (((a*2+0)*2+0)*8 + h)*32 + lane]
                     + sm[SSC + (((a*2+0)*2+1)*8 + h)*32 + lane];
            float v1 = (lane < 17) ? sm[SSC + (((a*2+1)*2+0)*8 + h)*32 + lane]
                                   + sm[SSC + (((a*2+1)*2+1)*8 + h)*32 + lane] : 0.f;
            v0 = (sm[SMK + a * 64 + lane] > 0.f) ? v0 * 0.25f : -1e9f;
            const int j1 = lane + 32;
            if (j1 < KP1) v1 = (sm[SMK + a * 64 + j1] > 0.f) ? v1 * 0.25f : -1e9f;
            else          v1 = -3.0e38f;
            float m = fmaxf(v0, v1);
            #pragma unroll
            for (int o = 16; o > 0; o >>= 1)
                m = fmaxf(m, __shfl_xor_sync(0xffffffffu, m, o));
            const float e0 = __expf(v0 - m);
            const float e1 = (j1 < KP1) ? __expf(v1 - m) : 0.f;
            float ssum = e0 + e1;
            #pragma unroll
            for (int o = 16; o > 0; o >>= 1)
                ssum += __shfl_xor_sync(0xffffffffu, ssum, o);
            const float inv = 1.0f / ssum;
            atth[a * 512 + lane * 8 + h] = __float2half(e0 * inv);
            if (j1 < KP1) atth[a * 512 + j1 * 8 + h] = __float2half(e1 * inv);
        }
    }
    __syncthreads();

    // ---- Phase G: u in HALF2 -> g_U[atom][c*8 + h] (uint4, coalesced) ----
    {
        const int c = tid & 127;
        const __half* kvc  = &kvh[a4 * KVAH + c];
        const __half* atth = (const __half*)sm + SATT * 2 + a4 * 512;
        __half2 acc2[4];
        #pragma unroll
        for (int i = 0; i < 4; i++) acc2[i] = __floats2half2_rn(0.f, 0.f);
        #pragma unroll 7
        for (int j = 0; j < KP1; j++) {
            const uint4 praw = *(const uint4*)&atth[j * 8];
            const __half2 kv2 = __half2half2(kvc[j * KVH]);
            acc2[0] = __hfma2(*(const __half2*)&praw.x, kv2, acc2[0]);
            acc2[1] = __hfma2(*(const __half2*)&praw.y, kv2, acc2[1]);
            acc2[2] = __hfma2(*(const __half2*)&praw.z, kv2, acc2[2]);
            acc2[3] = __hfma2(*(const __half2*)&praw.w, kv2, acc2[3]);
        }
        uint4 uu;
        __half2* up = (__half2*)&uu;
        up[0] = acc2[0]; up[1] = acc2[1]; up[2] = acc2[2]; up[3] = acc2[3];
        *(uint4*)&g_U[(u32)(atomBase + a4) * 1024 + c * 8] = uu;
    }
}

} // namespace

extern "C" void kernel_launch(void* const* d_in, const int* in_sizes, int n_in,
                              void* d_out, int out_size) {
    (void)in_sizes; (void)n_in; (void)out_size;
    const float* positions = (const float*)d_in[0];
    const int*   z         = (const int*)  d_in[1];
    const int*   neighbors = (const int*)  d_in[2];
    const float* nmask     = (const float*)d_in[3];
    const float* embedding = (const float*)d_in[4];
    const float* filtW     = (const float*)d_in[5];
    const float* filtb     = (const float*)d_in[6];
    const float* Wq        = (const float*)d_in[7];
    const float* Wk        = (const float*)d_in[8];
    const float* Wv        = (const float*)d_in[9];
    const float* Wo        = (const float*)d_in[10];
    float* out = (float*)d_out;

    cudaFuncSetAttribute(proj_kernel,
                         cudaFuncAttributeMaxDynamicSharedMemorySize, P_SMEM);
    cudaFuncSetAttribute(outp_kernel,
                         cudaFuncAttributeMaxDynamicSharedMemorySize, O_SMEM);
    cudaFuncSetAttribute(tdt_kernel,
                         cudaFuncAttributeMaxDynamicSharedMemorySize, SMEM_BYTES);

    prep_kernel<<<1024, 256>>>(Wq, Wk, Wv, Wo);
    proj_kernel<<<NATOM / 64, 512, P_SMEM>>>(z, embedding);
    tdt_kernel<<<NATOM / ATOMS, THREADS, SMEM_BYTES>>>(
        positions, z, neighbors, nmask, embedding, filtW, filtb);
    outp_kernel<<<NATOM / 64, 512, O_SMEM>>>(z, embedding, out);
}